// round 13
// baseline (speedup 1.0000x reference)
#include <cuda_runtime.h>
#include <cuda_bf16.h>
#include <cuda_fp16.h>
#include <cstdint>

// ---------------------------------------------------------------------------
// Problem constants
#define B_   2
#define S_   2048
#define D_   1024
#define H_   16
#define DH_  64
#define MTOT (B_*S_)     // 4096
#define NQKV (3*D_)      // 3072

// softmax exp2 folding: Q scaled by (1/8)*log2(e)
#define QSCALE 0.1803368801111244f

// ---------------------------------------------------------------------------
// Device-global scratch (allocation-free), all fp16
__device__ __half g_xHi[MTOT*D_];    // x split, [m][k]
__device__ __half g_xLo[MTOT*D_];
__device__ __half g_w [NQKV*D_];     // qkv weights (single fp16), [n][k], n=z*1024+h*64+e
__device__ __half g_wo[D_*D_];       // Wo^T (single fp16), [n][k]
__device__ __half g_cHi[MTOT*D_];    // ctx split, [m][k]
__device__ __half g_cLo[MTOT*D_];

// attention operands, layout [b*s][h*64+e] (same as GEMM C tile -> coalesced epilogue)
__device__ __half g_qHi[MTOT*D_];    // scaled by QSCALE
__device__ __half g_qLo[MTOT*D_];
__device__ __half g_kHi[MTOT*D_];
__device__ __half g_vHi[MTOT*D_];
__device__ __half g_vLo[MTOT*D_];

// ---------------------------------------------------------------------------
// Baseline-PTX helpers (no sm_103a-only features)
__device__ __forceinline__ uint32_t smem_u32(const void* p) {
    uint32_t a;
    asm("{ .reg .u64 t; cvta.to.shared.u64 t, %1; cvt.u32.u64 %0, t; }" : "=r"(a) : "l"(p));
    return a;
}
__device__ __forceinline__ void ldsm4(uint32_t* r, uint32_t addr) {
    asm volatile("ldmatrix.sync.aligned.m8n8.x4.shared.b16 {%0,%1,%2,%3}, [%4];"
        : "=r"(r[0]), "=r"(r[1]), "=r"(r[2]), "=r"(r[3]) : "r"(addr));
}
__device__ __forceinline__ void ldsm4t(uint32_t* r, uint32_t addr) {
    asm volatile("ldmatrix.sync.aligned.m8n8.x4.trans.shared.b16 {%0,%1,%2,%3}, [%4];"
        : "=r"(r[0]), "=r"(r[1]), "=r"(r[2]), "=r"(r[3]) : "r"(addr));
}
__device__ __forceinline__ void mma_f16(float* c, const uint32_t* a, const uint32_t* b) {
    asm volatile("mma.sync.aligned.m16n8k16.row.col.f32.f16.f16.f32 "
        "{%0,%1,%2,%3}, {%4,%5,%6,%7}, {%8,%9}, {%0,%1,%2,%3};"
        : "+f"(c[0]), "+f"(c[1]), "+f"(c[2]), "+f"(c[3])
        : "r"(a[0]), "r"(a[1]), "r"(a[2]), "r"(a[3]), "r"(b[0]), "r"(b[1]));
}
__device__ __forceinline__ void cpasync16(uint32_t dst, const void* src) {
    asm volatile("cp.async.cg.shared.global [%0], [%1], 16;" :: "r"(dst), "l"(src) : "memory");
}
#define CP_COMMIT() asm volatile("cp.async.commit_group;" ::: "memory")
#define CP_WAIT(n)  asm volatile("cp.async.wait_group %0;" :: "n"(n) : "memory")

__device__ __forceinline__ float ex2(float x) {
    float y;
    asm("ex2.approx.f32 %0, %1;" : "=f"(y) : "f"(x));
    return y;
}

// pack two fp32 into f16x2 hi-word and lo-word (x -> low 16 bits)
__device__ __forceinline__ void pack_hl_f16(float x, float y, uint32_t& hi, uint32_t& lo) {
    __half hx = __float2half_rn(x), hy = __float2half_rn(y);
    __half lx = __float2half_rn(x - __half2float(hx));
    __half ly = __float2half_rn(y - __half2float(hy));
    __half2 h2 = __halves2half2(hx, hy);
    __half2 l2 = __halves2half2(lx, ly);
    hi = *(uint32_t*)&h2;
    lo = *(uint32_t*)&l2;
}
__device__ __forceinline__ uint32_t pack_f16(float x, float y) {
    __half2 h2 = __floats2half2_rn(x, y);
    return *(uint32_t*)&h2;
}

// ---------------------------------------------------------------------------
// Conversion kernels
__global__ __launch_bounds__(256) void cvt_x_kernel(const float* __restrict__ x) {
    int i = blockIdx.x * 256 + threadIdx.x;
    float4 v = ((const float4*)x)[i];
    uint32_t h0, l0, h1, l1;
    pack_hl_f16(v.x, v.y, h0, l0);
    pack_hl_f16(v.z, v.w, h1, l1);
    ((uint32_t*)g_xHi)[2*i]   = h0;
    ((uint32_t*)g_xHi)[2*i+1] = h1;
    ((uint32_t*)g_xLo)[2*i]   = l0;
    ((uint32_t*)g_xLo)[2*i+1] = l1;
}

// Transpose-convert: in [R][C] fp32 (slab per blockIdx.z) -> out[c][r] single fp16
__global__ __launch_bounds__(256)
void cvt_T_kernel(const float* __restrict__ in, __half* __restrict__ oh, int R, int C)
{
    __shared__ float tb[32][33];
    const size_t slab = (size_t)blockIdx.z * R * C;
    const float* src = in + slab;
    const int r0 = blockIdx.x * 32, c0 = blockIdx.y * 32;
    const int tx = threadIdx.x, ty = threadIdx.y;   // (32, 8)
#pragma unroll
    for (int i = 0; i < 4; i++)
        tb[ty + i*8][tx] = src[(size_t)(r0 + ty + i*8) * C + (c0 + tx)];
    __syncthreads();
#pragma unroll
    for (int i = 0; i < 4; i++) {
        size_t idx = slab + (size_t)(c0 + ty + i*8) * R + (r0 + tx);
        oh[idx] = __float2half_rn(tb[tx][ty + i*8]);
    }
}

// ---------------------------------------------------------------------------
// mma.sync GEMM: C[128x128] per CTA, K=1024 in 16 chunks of 64.
// fp16 2-term: (Ah + Al) x B(single fp16). Stage = [Ah][Al][B], 3 tiles.
// __launch_bounds__(256,2): 2 CTAs/SM (smem 2x110.6KB = 221KB <= 228KB).
#define RB     144
#define GTILE  (128*RB)                 // 18432
#define GEMM_SMEM (2*3*GTILE)           // 110592

template <int MODE>
__global__ __launch_bounds__(256, 2)
void mma_gemm(const float* __restrict__ bq, const float* __restrict__ bk,
              const float* __restrict__ bv, const float* __restrict__ bo,
              float* __restrict__ out)
{
    extern __shared__ char smem[];
    const uint32_t sb = smem_u32(smem);
    const int tid = threadIdx.x, w = tid >> 5, t = tid & 31;
    const int m0 = blockIdx.y * 128, n0 = blockIdx.x * 128;
    const int mw = (w & 3) * 32, nw = (w >> 2) * 64;

    const __half* Ah = (MODE == 0) ? g_xHi : g_cHi;
    const __half* Al = (MODE == 0) ? g_xLo : g_cLo;
    const __half* Bw = (MODE == 0) ? g_w   : g_wo;

    float c[2][8][4];
#pragma unroll
    for (int i = 0; i < 2; i++)
#pragma unroll
        for (int j = 0; j < 8; j++)
#pragma unroll
            for (int q = 0; q < 4; q++) c[i][j][q] = 0.f;

    const int u  = tid & 7;
    const int r0 = tid >> 3;

    // ---- prologue: load chunk 0 into stage 0
#pragma unroll
    for (int p = 0; p < 4; p++) {
        int row = r0 + p * 32;
        uint32_t d = sb + row * RB + u * 16;
        cpasync16(d,             Ah + (size_t)(m0 + row) * D_ + u * 8);
        cpasync16(d + GTILE,     Al + (size_t)(m0 + row) * D_ + u * 8);
        cpasync16(d + 2*GTILE,   Bw + (size_t)(n0 + row) * D_ + u * 8);
    }
    CP_COMMIT();

    for (int kb = 0; kb < 16; kb++) {
        if (kb < 15) {
            const int st = (kb + 1) & 1;
            const int ko = (kb + 1) * 64;
#pragma unroll
            for (int p = 0; p < 4; p++) {
                int row = r0 + p * 32;
                uint32_t d = sb + st * 3 * GTILE + row * RB + u * 16;
                cpasync16(d,           Ah + (size_t)(m0 + row) * D_ + ko + u * 8);
                cpasync16(d + GTILE,   Al + (size_t)(m0 + row) * D_ + ko + u * 8);
                cpasync16(d + 2*GTILE, Bw + (size_t)(n0 + row) * D_ + ko + u * 8);
            }
            CP_COMMIT();
            CP_WAIT(1);
        } else {
            CP_WAIT(0);
        }
        __syncthreads();

        const uint32_t base = sb + (kb & 1) * 3 * GTILE;
#pragma unroll
        for (int ks = 0; ks < 4; ks++) {
            uint32_t aH[2][4], aL[2][4];
#pragma unroll
            for (int mt = 0; mt < 2; mt++) {
                uint32_t ad = base + (mw + 16*mt + (t & 15)) * RB + ks * 32 + (t >> 4) * 16;
                ldsm4(aH[mt], ad);
                ldsm4(aL[mt], ad + GTILE);
            }
#pragma unroll
            for (int np = 0; np < 4; np++) {
                uint32_t bH[4];
                uint32_t ad = base + 2*GTILE
                            + (nw + np*16 + ((t >> 4) << 3) + (t & 7)) * RB
                            + ks * 32 + ((t >> 3) & 1) * 16;
                ldsm4(bH, ad);
#pragma unroll
                for (int mt = 0; mt < 2; mt++) {
                    mma_f16(c[mt][2*np],   aH[mt], bH);
                    mma_f16(c[mt][2*np],   aL[mt], bH);
                    mma_f16(c[mt][2*np+1], aH[mt], bH + 2);
                    mma_f16(c[mt][2*np+1], aL[mt], bH + 2);
                }
            }
        }
        __syncthreads();
    }

    // ---- epilogue (both modes now fully coalesced: 16B segments per quad)
    const int g = t >> 2, i2 = (t & 3) * 2;
    if (MODE == 0) {
        const int z = n0 >> 10;
        const float scale = (z == 0) ? QSCALE : 1.0f;   // log2e folded into Q
        const float* bias = (z == 0) ? bq : (z == 1) ? bk : bv;
        __half* dHi = (z == 0) ? g_qHi : (z == 1) ? g_kHi : g_vHi;
        __half* dLo = (z == 0) ? g_qLo : g_vLo;   // unused for z==1
        const int nin0 = n0 & 1023;               // column base within [m][1024] layout
#pragma unroll
        for (int mt = 0; mt < 2; mt++) {
#pragma unroll
            for (int rr = 0; rr < 2; rr++) {
                const int m = m0 + mw + 16*mt + g + rr*8;
#pragma unroll
                for (int nt = 0; nt < 8; nt++) {
                    const int col = nw + nt*8 + i2;
                    const int nin = nin0 + col;
                    float v0 = (c[mt][nt][rr*2+0] + bias[nin])   * scale;
                    float v1 = (c[mt][nt][rr*2+1] + bias[nin+1]) * scale;
                    size_t off = (size_t)m * D_ + nin;
                    if (z == 1) {
                        *(uint32_t*)(dHi + off) = pack_f16(v0, v1);
                    } else {
                        uint32_t hi, lo;
                        pack_hl_f16(v0, v1, hi, lo);
                        *(uint32_t*)(dHi + off) = hi;
                        *(uint32_t*)(dLo + off) = lo;
                    }
                }
            }
        }
    } else {
#pragma unroll
        for (int mt = 0; mt < 2; mt++) {
#pragma unroll
            for (int rr = 0; rr < 2; rr++) {
                const int m = m0 + mw + 16*mt + g + rr*8;
#pragma unroll
                for (int nt = 0; nt < 8; nt++) {
                    const int col = n0 + nw + nt*8 + i2;
                    float2 v;
                    v.x = c[mt][nt][rr*2+0] + bo[col];
                    v.y = c[mt][nt][rr*2+1] + bo[col+1];
                    *(float2*)(out + (size_t)m * D_ + col) = v;
                }
            }
        }
    }
}

// ---------------------------------------------------------------------------
// mma.sync flash attention, fp16 2-term, K/V double-buffered, Q hoisted to regs.
// 128 q-rows per CTA, 8 warps x 16 rows, 64-key blocks.
// Q/K/V global layout: [b*s][h*64+e]  (row stride D_ halves).
#define QT    (128*RB)     // 18432
#define KT    (64*RB)      // 9216
#define KVST  (3*KT)       // 27648
#define ATTN_SMEM (2*QT + 2*KVST)

__global__ __launch_bounds__(256, 2)
void mma_attn()
{
    extern __shared__ char smem[];
    const uint32_t sb = smem_u32(smem);
    const int tid = threadIdx.x, w = tid >> 5, t = tid & 31;
    const int qb = blockIdx.x, bh = blockIdx.y;
    const int batch = bh >> 4, h = bh & 15;
    const size_t rowbase = (size_t)batch * S_;      // global row = rowbase + s
    const int hcol = h * DH_;                       // column offset within 1024-wide row

    const uint32_t QH = sb, QL = sb + QT;
    const uint32_t KV0 = sb + 2*QT;     // stage s at KV0 + s*KVST: [Kh][Vh][Vl]

    const int u = tid & 7, r0 = tid >> 3;

    // ---- prologue group 1: Q tiles only (so Q can be consumed early)
#pragma unroll
    for (int p = 0; p < 4; p++) {
        int row = r0 + p * 32;
        size_t src = (rowbase + qb * 128 + row) * D_ + hcol + u * 8;
        cpasync16(QH + row * RB + u * 16, g_qHi + src);
        cpasync16(QL + row * RB + u * 16, g_qLo + src);
    }
    CP_COMMIT();
    // ---- prologue group 2: K/V block 0
#pragma unroll
    for (int p = 0; p < 2; p++) {
        int row = r0 + p * 32;
        size_t src = (rowbase + row) * D_ + hcol + u * 8;
        uint32_t d = KV0 + row * RB + u * 16;
        cpasync16(d,          g_kHi + src);
        cpasync16(d + KT,     g_vHi + src);
        cpasync16(d + 2*KT,   g_vLo + src);
    }
    CP_COMMIT();

    // ---- hoist Q fragments into registers (loop-invariant)
    CP_WAIT(1);          // Q group done (KV0 may still be in flight)
    __syncthreads();
    uint32_t qaH[4][4], qaL[4][4];
#pragma unroll
    for (int ks = 0; ks < 4; ks++) {
        uint32_t ad = QH + (w * 16 + (t & 15)) * RB + ks * 32 + (t >> 4) * 16;
        ldsm4(qaH[ks], ad);
        ldsm4(qaL[ks], ad + QT);
    }

    float o[8][4];
#pragma unroll
    for (int j = 0; j < 8; j++)
#pragma unroll
        for (int q = 0; q < 4; q++) o[j][q] = 0.f;
    float mr0 = -1e30f, mr1 = -1e30f, lr0 = 0.f, lr1 = 0.f;

    for (int kb = 0; kb < 32; kb++) {
        if (kb < 31) {
            const uint32_t st = KV0 + ((kb + 1) & 1) * KVST;
#pragma unroll
            for (int p = 0; p < 2; p++) {
                int row = r0 + p * 32;
                size_t src = (rowbase + (kb + 1) * 64 + row) * D_ + hcol + u * 8;
                uint32_t d = st + row * RB + u * 16;
                cpasync16(d,          g_kHi + src);
                cpasync16(d + KT,     g_vHi + src);
                cpasync16(d + 2*KT,   g_vLo + src);
            }
            CP_COMMIT();
            CP_WAIT(1);
        } else {
            CP_WAIT(0);
        }
        __syncthreads();

        const uint32_t KH = KV0 + (kb & 1) * KVST;
        const uint32_t VH = KH + KT, VL = KH + 2*KT;

        // ---- S(log2 domain) = Q K^T: (Qh + Ql) x Kh
        float s[8][4];
#pragma unroll
        for (int j = 0; j < 8; j++)
#pragma unroll
            for (int q = 0; q < 4; q++) s[j][q] = 0.f;
#pragma unroll
        for (int ks = 0; ks < 4; ks++) {
#pragma unroll
            for (int np = 0; np < 4; np++) {
                uint32_t bH[4];
                uint32_t bd = KH + (np*16 + ((t >> 4) << 3) + (t & 7)) * RB
                            + ks * 32 + ((t >> 3) & 1) * 16;
                ldsm4(bH, bd);
                mma_f16(s[2*np],   qaH[ks], bH);
                mma_f16(s[2*np],   qaL[ks], bH);
                mma_f16(s[2*np+1], qaH[ks], bH + 2);
                mma_f16(s[2*np+1], qaL[ks], bH + 2);
            }
        }

        // ---- online softmax in log2 domain (rows g and g+8, row within warp)
        float rmax0 = -1e30f, rmax1 = -1e30f;
#pragma unroll
        for (int j = 0; j < 8; j++) {
            rmax0 = fmaxf(rmax0, fmaxf(s[j][0], s[j][1]));
            rmax1 = fmaxf(rmax1, fmaxf(s[j][2], s[j][3]));
        }
#pragma unroll
        for (int off = 1; off <= 2; off <<= 1) {
            rmax0 = fmaxf(rmax0, __shfl_xor_sync(0xffffffffu, rmax0, off));
            rmax1 = fmaxf(rmax1, __shfl_xor_sync(0xffffffffu, rmax1, off));
        }
        float mn0 = fmaxf(mr0, rmax0), mn1 = fmaxf(mr1, rmax1);
        float corr0 = ex2(mr0 - mn0), corr1 = ex2(mr1 - mn1);
        mr0 = mn0; mr1 = mn1;

        float sum0 = 0.f, sum1 = 0.f;
#pragma unroll
        for (int j = 0; j < 8; j++) {
            s[j][0] = ex2(s[j][0] - mn0);
            s[j][1] = ex2(s[j][1] - mn0);
            s[j][2] = ex2(s[j][2] - mn1);
            s[j][3] = ex2(s[j][3] - mn1);
            sum0 += s[j][0] + s[j][1];
            sum1 += s[j][2] + s[j][3];
        }
#pragma unroll
        for (int off = 1; off <= 2; off <<= 1) {
            sum0 += __shfl_xor_sync(0xffffffffu, sum0, off);
            sum1 += __shfl_xor_sync(0xffffffffu, sum1, off);
        }
        lr0 = lr0 * corr0 + sum0;
        lr1 = lr1 * corr1 + sum1;
#pragma unroll
        for (int j = 0; j < 8; j++) {
            o[j][0] *= corr0; o[j][1] *= corr0;
            o[j][2] *= corr1; o[j][3] *= corr1;
        }

        // ---- pack P (single fp16) into PV A-fragments
        uint32_t pH[4][4];
#pragma unroll
        for (int kk = 0; kk < 4; kk++) {
            pH[kk][0] = pack_f16(s[2*kk][0],   s[2*kk][1]);
            pH[kk][1] = pack_f16(s[2*kk][2],   s[2*kk][3]);
            pH[kk][2] = pack_f16(s[2*kk+1][0], s[2*kk+1][1]);
            pH[kk][3] = pack_f16(s[2*kk+1][2], s[2*kk+1][3]);
        }

        // ---- O += P * (Vh + Vl), V via ldmatrix.trans
#pragma unroll
        for (int kk = 0; kk < 4; kk++) {
#pragma unroll
            for (int jp = 0; jp < 4; jp++) {
                uint32_t vHf[4], vLf[4];
                uint32_t vd = VH + (kk*16 + (t & 7) + (((t >> 3) & 1) << 3)) * RB
                            + jp * 32 + ((t >> 4) << 4);
                ldsm4t(vHf, vd);
                ldsm4t(vLf, vd + KT);
                mma_f16(o[2*jp],   pH[kk], vHf);
                mma_f16(o[2*jp],   pH[kk], vLf);
                mma_f16(o[2*jp+1], pH[kk], vHf + 2);
                mma_f16(o[2*jp+1], pH[kk], vLf + 2);
            }
        }

        __syncthreads();   // stage (kb&1) fully consumed before iter kb+1 refills it
    }

    // ---- epilogue: ctx[b*S+s][h*64+e] as fp16 hi/lo
    const float inv0 = 1.0f / lr0, inv1 = 1.0f / lr1;
    const int srow = qb * 128 + w * 16 + (t >> 2);
    const int i2 = (t & 3) * 2;
#pragma unroll
    for (int nt = 0; nt < 8; nt++) {
        const int col = hcol + nt * 8 + i2;
        uint32_t hi, lo;
        size_t off0 = (rowbase + srow) * D_ + col;
        pack_hl_f16(o[nt][0] * inv0, o[nt][1] * inv0, hi, lo);
        *(uint32_t*)(g_cHi + off0) = hi;
        *(uint32_t*)(g_cLo + off0) = lo;
        size_t off1 = (rowbase + srow + 8) * D_ + col;
        pack_hl_f16(o[nt][2] * inv1, o[nt][3] * inv1, hi, lo);
        *(uint32_t*)(g_cHi + off1) = hi;
        *(uint32_t*)(g_cLo + off1) = lo;
    }
}

// ---------------------------------------------------------------------------
extern "C" void kernel_launch(void* const* d_in, const int* in_sizes, int n_in,
                              void* d_out, int out_size)
{
    const float* x  = (const float*)d_in[0];
    const float* Wq = (const float*)d_in[1];
    const float* bq = (const float*)d_in[2];
    const float* Wk = (const float*)d_in[3];
    const float* bk = (const float*)d_in[4];
    const float* Wv = (const float*)d_in[5];
    const float* bv = (const float*)d_in[6];
    const float* Wo = (const float*)d_in[7];
    const float* bo = (const float*)d_in[8];
    float* out = (float*)d_out;

    static bool attr_done = false;
    if (!attr_done) {
        cudaFuncSetAttribute(mma_gemm<0>, cudaFuncAttributeMaxDynamicSharedMemorySize, GEMM_SMEM);
        cudaFuncSetAttribute(mma_gemm<1>, cudaFuncAttributeMaxDynamicSharedMemorySize, GEMM_SMEM);
        cudaFuncSetAttribute(mma_attn,    cudaFuncAttributeMaxDynamicSharedMemorySize, ATTN_SMEM);
        attr_done = true;
    }

    // operand prep: x -> fp16 hi/lo, weights -> single fp16 transposed
    cvt_x_kernel<<<MTOT * D_ / 4 / 256, 256>>>(x);
    __half *wp, *wop;
    cudaGetSymbolAddress((void**)&wp,  g_w);
    cudaGetSymbolAddress((void**)&wop, g_wo);
    dim3 tT(32, 8);
    cvt_T_kernel<<<dim3(D_/32, DH_/32, H_), tT>>>(Wq, wp,             D_, DH_);
    cvt_T_kernel<<<dim3(D_/32, DH_/32, H_), tT>>>(Wk, wp + 1024*D_,   D_, DH_);
    cvt_T_kernel<<<dim3(D_/32, DH_/32, H_), tT>>>(Wv, wp + 2048*D_,   D_, DH_);
    cvt_T_kernel<<<dim3(D_/32, D_/32, 1),   tT>>>(Wo, wop,            D_, D_);

    // fused QKV projection (fp16 2-term) -> q/k/v fp16 [b*s][h*64+e]
    mma_gemm<0><<<dim3(NQKV/128, MTOT/128), 256, GEMM_SMEM>>>(bq, bk, bv, bo, out);

    // flash attention (fp16 2-term tensor cores) -> ctx fp16 hi/lo
    mma_attn<<<dim3(S_/128, B_*H_), 256, ATTN_SMEM>>>();

    // output projection (fp16 2-term)
    mma_gemm<1><<<dim3(D_/128, MTOT/128), 256, GEMM_SMEM>>>(bq, bk, bv, bo, out);
}

// round 15
// speedup vs baseline: 1.1220x; 1.1220x over previous
#include <cuda_runtime.h>
#include <cuda_bf16.h>
#include <cuda_fp16.h>
#include <cstdint>

// ---------------------------------------------------------------------------
// Problem constants
#define B_   2
#define S_   2048
#define D_   1024
#define H_   16
#define DH_  64
#define MTOT (B_*S_)     // 4096
#define NQKV (3*D_)      // 3072

// softmax exp2 folding: Q scaled by (1/8)*log2(e)
#define QSCALE 0.1803368801111244f

// ---------------------------------------------------------------------------
// Device-global scratch (allocation-free), all fp16
__device__ __half g_xHi[MTOT*D_];    // x split, [m][k]
__device__ __half g_xLo[MTOT*D_];
__device__ __half g_w [NQKV*D_];     // qkv weights (single fp16), [n][k], n=z*1024+h*64+e
__device__ __half g_wo[D_*D_];       // Wo^T (single fp16), [n][k]
__device__ __half g_cHi[MTOT*D_];    // ctx split, [m][k]
__device__ __half g_cLo[MTOT*D_];

// attention operands, layout [b*s][h*64+e]
__device__ __half g_qHi[MTOT*D_];    // scaled by QSCALE
__device__ __half g_qLo[MTOT*D_];
__device__ __half g_kHi[MTOT*D_];
__device__ __half g_vHi[MTOT*D_];    // V single fp16 (lo term dropped)

// ---------------------------------------------------------------------------
// Baseline-PTX helpers (no sm_103a-only features)
__device__ __forceinline__ uint32_t smem_u32(const void* p) {
    uint32_t a;
    asm("{ .reg .u64 t; cvta.to.shared.u64 t, %1; cvt.u32.u64 %0, t; }" : "=r"(a) : "l"(p));
    return a;
}
__device__ __forceinline__ void ldsm4(uint32_t* r, uint32_t addr) {
    asm volatile("ldmatrix.sync.aligned.m8n8.x4.shared.b16 {%0,%1,%2,%3}, [%4];"
        : "=r"(r[0]), "=r"(r[1]), "=r"(r[2]), "=r"(r[3]) : "r"(addr));
}
__device__ __forceinline__ void ldsm4t(uint32_t* r, uint32_t addr) {
    asm volatile("ldmatrix.sync.aligned.m8n8.x4.trans.shared.b16 {%0,%1,%2,%3}, [%4];"
        : "=r"(r[0]), "=r"(r[1]), "=r"(r[2]), "=r"(r[3]) : "r"(addr));
}
__device__ __forceinline__ void mma_f16(float* c, const uint32_t* a, const uint32_t* b) {
    asm volatile("mma.sync.aligned.m16n8k16.row.col.f32.f16.f16.f32 "
        "{%0,%1,%2,%3}, {%4,%5,%6,%7}, {%8,%9}, {%0,%1,%2,%3};"
        : "+f"(c[0]), "+f"(c[1]), "+f"(c[2]), "+f"(c[3])
        : "r"(a[0]), "r"(a[1]), "r"(a[2]), "r"(a[3]), "r"(b[0]), "r"(b[1]));
}
__device__ __forceinline__ void cpasync16(uint32_t dst, const void* src) {
    asm volatile("cp.async.cg.shared.global [%0], [%1], 16;" :: "r"(dst), "l"(src) : "memory");
}
#define CP_COMMIT() asm volatile("cp.async.commit_group;" ::: "memory")
#define CP_WAIT(n)  asm volatile("cp.async.wait_group %0;" :: "n"(n) : "memory")

__device__ __forceinline__ float ex2(float x) {
    float y;
    asm("ex2.approx.f32 %0, %1;" : "=f"(y) : "f"(x));
    return y;
}

// pack two fp32 into f16x2 hi-word and lo-word (x -> low 16 bits)
__device__ __forceinline__ void pack_hl_f16(float x, float y, uint32_t& hi, uint32_t& lo) {
    __half hx = __float2half_rn(x), hy = __float2half_rn(y);
    __half lx = __float2half_rn(x - __half2float(hx));
    __half ly = __float2half_rn(y - __half2float(hy));
    __half2 h2 = __halves2half2(hx, hy);
    __half2 l2 = __halves2half2(lx, ly);
    hi = *(uint32_t*)&h2;
    lo = *(uint32_t*)&l2;
}
__device__ __forceinline__ uint32_t pack_f16(float x, float y) {
    __half2 h2 = __floats2half2_rn(x, y);
    return *(uint32_t*)&h2;
}

// ---------------------------------------------------------------------------
// Conversion kernels
__global__ __launch_bounds__(256) void cvt_x_kernel(const float* __restrict__ x) {
    int i = blockIdx.x * 256 + threadIdx.x;
    float4 v = ((const float4*)x)[i];
    uint32_t h0, l0, h1, l1;
    pack_hl_f16(v.x, v.y, h0, l0);
    pack_hl_f16(v.z, v.w, h1, l1);
    ((uint32_t*)g_xHi)[2*i]   = h0;
    ((uint32_t*)g_xHi)[2*i+1] = h1;
    ((uint32_t*)g_xLo)[2*i]   = l0;
    ((uint32_t*)g_xLo)[2*i+1] = l1;
}

// Transpose-convert: in [R][C] fp32 (slab per blockIdx.z) -> out[c][r] single fp16
__global__ __launch_bounds__(256)
void cvt_T_kernel(const float* __restrict__ in, __half* __restrict__ oh, int R, int C)
{
    __shared__ float tb[32][33];
    const size_t slab = (size_t)blockIdx.z * R * C;
    const float* src = in + slab;
    const int r0 = blockIdx.x * 32, c0 = blockIdx.y * 32;
    const int tx = threadIdx.x, ty = threadIdx.y;   // (32, 8)
#pragma unroll
    for (int i = 0; i < 4; i++)
        tb[ty + i*8][tx] = src[(size_t)(r0 + ty + i*8) * C + (c0 + tx)];
    __syncthreads();
#pragma unroll
    for (int i = 0; i < 4; i++) {
        size_t idx = slab + (size_t)(c0 + ty + i*8) * R + (r0 + tx);
        oh[idx] = __float2half_rn(tb[tx][ty + i*8]);
    }
}

// ---------------------------------------------------------------------------
// mma.sync GEMM: C[128x128] per CTA, K=1024 in 16 chunks of 64.
// fp16 2-term: (Ah + Al) x B(single fp16). Stage = [Ah][Al][B], 3 tiles.
// __launch_bounds__(256,2): 2 CTAs/SM (smem 2x110.6KB = 221KB <= 228KB).
#define RB     144
#define GTILE  (128*RB)                 // 18432
#define GEMM_SMEM (2*3*GTILE)           // 110592

template <int MODE>
__global__ __launch_bounds__(256, 2)
void mma_gemm(const float* __restrict__ bq, const float* __restrict__ bk,
              const float* __restrict__ bv, const float* __restrict__ bo,
              float* __restrict__ out)
{
    extern __shared__ char smem[];
    const uint32_t sb = smem_u32(smem);
    const int tid = threadIdx.x, w = tid >> 5, t = tid & 31;
    const int m0 = blockIdx.y * 128, n0 = blockIdx.x * 128;
    const int mw = (w & 3) * 32, nw = (w >> 2) * 64;

    const __half* Ah = (MODE == 0) ? g_xHi : g_cHi;
    const __half* Al = (MODE == 0) ? g_xLo : g_cLo;
    const __half* Bw = (MODE == 0) ? g_w   : g_wo;

    float c[2][8][4];
#pragma unroll
    for (int i = 0; i < 2; i++)
#pragma unroll
        for (int j = 0; j < 8; j++)
#pragma unroll
            for (int q = 0; q < 4; q++) c[i][j][q] = 0.f;

    const int u  = tid & 7;
    const int r0 = tid >> 3;

    // ---- prologue: load chunk 0 into stage 0
#pragma unroll
    for (int p = 0; p < 4; p++) {
        int row = r0 + p * 32;
        uint32_t d = sb + row * RB + u * 16;
        cpasync16(d,             Ah + (size_t)(m0 + row) * D_ + u * 8);
        cpasync16(d + GTILE,     Al + (size_t)(m0 + row) * D_ + u * 8);
        cpasync16(d + 2*GTILE,   Bw + (size_t)(n0 + row) * D_ + u * 8);
    }
    CP_COMMIT();

    for (int kb = 0; kb < 16; kb++) {
        if (kb < 15) {
            const int st = (kb + 1) & 1;
            const int ko = (kb + 1) * 64;
#pragma unroll
            for (int p = 0; p < 4; p++) {
                int row = r0 + p * 32;
                uint32_t d = sb + st * 3 * GTILE + row * RB + u * 16;
                cpasync16(d,           Ah + (size_t)(m0 + row) * D_ + ko + u * 8);
                cpasync16(d + GTILE,   Al + (size_t)(m0 + row) * D_ + ko + u * 8);
                cpasync16(d + 2*GTILE, Bw + (size_t)(n0 + row) * D_ + ko + u * 8);
            }
            CP_COMMIT();
            CP_WAIT(1);
        } else {
            CP_WAIT(0);
        }
        __syncthreads();

        const uint32_t base = sb + (kb & 1) * 3 * GTILE;
#pragma unroll
        for (int ks = 0; ks < 4; ks++) {
            uint32_t aH[2][4], aL[2][4];
#pragma unroll
            for (int mt = 0; mt < 2; mt++) {
                uint32_t ad = base + (mw + 16*mt + (t & 15)) * RB + ks * 32 + (t >> 4) * 16;
                ldsm4(aH[mt], ad);
                ldsm4(aL[mt], ad + GTILE);
            }
#pragma unroll
            for (int np = 0; np < 4; np++) {
                uint32_t bH[4];
                uint32_t ad = base + 2*GTILE
                            + (nw + np*16 + ((t >> 4) << 3) + (t & 7)) * RB
                            + ks * 32 + ((t >> 3) & 1) * 16;
                ldsm4(bH, ad);
#pragma unroll
                for (int mt = 0; mt < 2; mt++) {
                    mma_f16(c[mt][2*np],   aH[mt], bH);
                    mma_f16(c[mt][2*np],   aL[mt], bH);
                    mma_f16(c[mt][2*np+1], aH[mt], bH + 2);
                    mma_f16(c[mt][2*np+1], aL[mt], bH + 2);
                }
            }
        }
        __syncthreads();
    }

    // ---- epilogue (coalesced 16B segments per quad)
    const int g = t >> 2, i2 = (t & 3) * 2;
    if (MODE == 0) {
        const int z = n0 >> 10;
        const float scale = (z == 0) ? QSCALE : 1.0f;   // log2e folded into Q
        const float* bias = (z == 0) ? bq : (z == 1) ? bk : bv;
        __half* dHi = (z == 0) ? g_qHi : (z == 1) ? g_kHi : g_vHi;
        const int nin0 = n0 & 1023;               // column base within [m][1024] layout
#pragma unroll
        for (int mt = 0; mt < 2; mt++) {
#pragma unroll
            for (int rr = 0; rr < 2; rr++) {
                const int m = m0 + mw + 16*mt + g + rr*8;
#pragma unroll
                for (int nt = 0; nt < 8; nt++) {
                    const int col = nw + nt*8 + i2;
                    const int nin = nin0 + col;
                    float v0 = (c[mt][nt][rr*2+0] + bias[nin])   * scale;
                    float v1 = (c[mt][nt][rr*2+1] + bias[nin+1]) * scale;
                    size_t off = (size_t)m * D_ + nin;
                    if (z == 0) {
                        uint32_t hi, lo;
                        pack_hl_f16(v0, v1, hi, lo);
                        *(uint32_t*)(dHi + off)   = hi;
                        *(uint32_t*)(g_qLo + off) = lo;
                    } else {
                        *(uint32_t*)(dHi + off) = pack_f16(v0, v1);  // K, V single fp16
                    }
                }
            }
        }
    } else {
#pragma unroll
        for (int mt = 0; mt < 2; mt++) {
#pragma unroll
            for (int rr = 0; rr < 2; rr++) {
                const int m = m0 + mw + 16*mt + g + rr*8;
#pragma unroll
                for (int nt = 0; nt < 8; nt++) {
                    const int col = n0 + nw + nt*8 + i2;
                    float2 v;
                    v.x = c[mt][nt][rr*2+0] + bo[col];
                    v.y = c[mt][nt][rr*2+1] + bo[col+1];
                    *(float2*)(out + (size_t)m * D_ + col) = v;
                }
            }
        }
    }
}

// ---------------------------------------------------------------------------
// mma.sync flash attention, fp16, K/V double-buffered, Q hoisted to regs.
// 128 q-rows per CTA, 8 warps x 16 rows, 64-key blocks.
// QK^T: (Qh + Ql) x Kh (2 MMAs). PV: P x Vh (1 MMA) — V lo-term dropped.
// Q/K/V global layout: [b*s][h*64+e].
// smem: Qhi/Qlo [128][72] + 2 stages x (Kh/Vh [64][72]) = 73728 B
#define QT    (128*RB)     // 18432
#define KT    (64*RB)      // 9216
#define KVST  (2*KT)       // 18432
#define ATTN_SMEM (2*QT + 2*KVST)

__global__ __launch_bounds__(256, 2)
void mma_attn()
{
    extern __shared__ char smem[];
    const uint32_t sb = smem_u32(smem);
    const int tid = threadIdx.x, w = tid >> 5, t = tid & 31;
    const int qb = blockIdx.x, bh = blockIdx.y;
    const int batch = bh >> 4, h = bh & 15;
    const size_t rowbase = (size_t)batch * S_;      // global row = rowbase + s
    const int hcol = h * DH_;                       // column offset within 1024-wide row

    const uint32_t QH = sb, QL = sb + QT;
    const uint32_t KV0 = sb + 2*QT;     // stage s at KV0 + s*KVST: [Kh][Vh]

    const int u = tid & 7, r0 = tid >> 3;

    // ---- prologue group 1: Q tiles only (so Q can be consumed early)
#pragma unroll
    for (int p = 0; p < 4; p++) {
        int row = r0 + p * 32;
        size_t src = (rowbase + qb * 128 + row) * D_ + hcol + u * 8;
        cpasync16(QH + row * RB + u * 16, g_qHi + src);
        cpasync16(QL + row * RB + u * 16, g_qLo + src);
    }
    CP_COMMIT();
    // ---- prologue group 2: K/V block 0
#pragma unroll
    for (int p = 0; p < 2; p++) {
        int row = r0 + p * 32;
        size_t src = (rowbase + row) * D_ + hcol + u * 8;
        uint32_t d = KV0 + row * RB + u * 16;
        cpasync16(d,          g_kHi + src);
        cpasync16(d + KT,     g_vHi + src);
    }
    CP_COMMIT();

    // ---- hoist Q fragments into registers (loop-invariant)
    CP_WAIT(1);          // Q group done (KV0 may still be in flight)
    __syncthreads();
    uint32_t qaH[4][4], qaL[4][4];
#pragma unroll
    for (int ks = 0; ks < 4; ks++) {
        uint32_t ad = QH + (w * 16 + (t & 15)) * RB + ks * 32 + (t >> 4) * 16;
        ldsm4(qaH[ks], ad);
        ldsm4(qaL[ks], ad + QT);
    }

    float o[8][4];
#pragma unroll
    for (int j = 0; j < 8; j++)
#pragma unroll
        for (int q = 0; q < 4; q++) o[j][q] = 0.f;
    float mr0 = -1e30f, mr1 = -1e30f, lr0 = 0.f, lr1 = 0.f;

    for (int kb = 0; kb < 32; kb++) {
        if (kb < 31) {
            const uint32_t st = KV0 + ((kb + 1) & 1) * KVST;
#pragma unroll
            for (int p = 0; p < 2; p++) {
                int row = r0 + p * 32;
                size_t src = (rowbase + (kb + 1) * 64 + row) * D_ + hcol + u * 8;
                uint32_t d = st + row * RB + u * 16;
                cpasync16(d,          g_kHi + src);
                cpasync16(d + KT,     g_vHi + src);
            }
            CP_COMMIT();
            CP_WAIT(1);
        } else {
            CP_WAIT(0);
        }
        __syncthreads();

        const uint32_t KH = KV0 + (kb & 1) * KVST;
        const uint32_t VH = KH + KT;

        // ---- S(log2 domain) = Q K^T: (Qh + Ql) x Kh
        float s[8][4];
#pragma unroll
        for (int j = 0; j < 8; j++)
#pragma unroll
            for (int q = 0; q < 4; q++) s[j][q] = 0.f;
#pragma unroll
        for (int ks = 0; ks < 4; ks++) {
#pragma unroll
            for (int np = 0; np < 4; np++) {
                uint32_t bH[4];
                uint32_t bd = KH + (np*16 + ((t >> 4) << 3) + (t & 7)) * RB
                            + ks * 32 + ((t >> 3) & 1) * 16;
                ldsm4(bH, bd);
                mma_f16(s[2*np],   qaH[ks], bH);
                mma_f16(s[2*np],   qaL[ks], bH);
                mma_f16(s[2*np+1], qaH[ks], bH + 2);
                mma_f16(s[2*np+1], qaL[ks], bH + 2);
            }
        }

        // ---- online softmax in log2 domain (rows g and g+8, row within warp)
        float rmax0 = -1e30f, rmax1 = -1e30f;
#pragma unroll
        for (int j = 0; j < 8; j++) {
            rmax0 = fmaxf(rmax0, fmaxf(s[j][0], s[j][1]));
            rmax1 = fmaxf(rmax1, fmaxf(s[j][2], s[j][3]));
        }
#pragma unroll
        for (int off = 1; off <= 2; off <<= 1) {
            rmax0 = fmaxf(rmax0, __shfl_xor_sync(0xffffffffu, rmax0, off));
            rmax1 = fmaxf(rmax1, __shfl_xor_sync(0xffffffffu, rmax1, off));
        }
        float mn0 = fmaxf(mr0, rmax0), mn1 = fmaxf(mr1, rmax1);
        float corr0 = ex2(mr0 - mn0), corr1 = ex2(mr1 - mn1);
        mr0 = mn0; mr1 = mn1;

        float sum0 = 0.f, sum1 = 0.f;
#pragma unroll
        for (int j = 0; j < 8; j++) {
            s[j][0] = ex2(s[j][0] - mn0);
            s[j][1] = ex2(s[j][1] - mn0);
            s[j][2] = ex2(s[j][2] - mn1);
            s[j][3] = ex2(s[j][3] - mn1);
            sum0 += s[j][0] + s[j][1];
            sum1 += s[j][2] + s[j][3];
        }
#pragma unroll
        for (int off = 1; off <= 2; off <<= 1) {
            sum0 += __shfl_xor_sync(0xffffffffu, sum0, off);
            sum1 += __shfl_xor_sync(0xffffffffu, sum1, off);
        }
        lr0 = lr0 * corr0 + sum0;
        lr1 = lr1 * corr1 + sum1;
#pragma unroll
        for (int j = 0; j < 8; j++) {
            o[j][0] *= corr0; o[j][1] *= corr0;
            o[j][2] *= corr1; o[j][3] *= corr1;
        }

        // ---- pack P (single fp16) into PV A-fragments
        uint32_t pH[4][4];
#pragma unroll
        for (int kk = 0; kk < 4; kk++) {
            pH[kk][0] = pack_f16(s[2*kk][0],   s[2*kk][1]);
            pH[kk][1] = pack_f16(s[2*kk][2],   s[2*kk][3]);
            pH[kk][2] = pack_f16(s[2*kk+1][0], s[2*kk+1][1]);
            pH[kk][3] = pack_f16(s[2*kk+1][2], s[2*kk+1][3]);
        }

        // ---- O += P * Vh, V via ldmatrix.trans (single term)
#pragma unroll
        for (int kk = 0; kk < 4; kk++) {
#pragma unroll
            for (int jp = 0; jp < 4; jp++) {
                uint32_t vHf[4];
                uint32_t vd = VH + (kk*16 + (t & 7) + (((t >> 3) & 1) << 3)) * RB
                            + jp * 32 + ((t >> 4) << 4);
                ldsm4t(vHf, vd);
                mma_f16(o[2*jp],   pH[kk], vHf);
                mma_f16(o[2*jp+1], pH[kk], vHf + 2);
            }
        }

        __syncthreads();   // stage (kb&1) fully consumed before iter kb+1 refills it
    }

    // ---- epilogue: ctx[b*S+s][h*64+e] as fp16 hi/lo
    const float inv0 = 1.0f / lr0, inv1 = 1.0f / lr1;
    const int srow = qb * 128 + w * 16 + (t >> 2);
    const int i2 = (t & 3) * 2;
#pragma unroll
    for (int nt = 0; nt < 8; nt++) {
        const int col = hcol + nt * 8 + i2;
        uint32_t hi, lo;
        size_t off0 = (rowbase + srow) * D_ + col;
        pack_hl_f16(o[nt][0] * inv0, o[nt][1] * inv0, hi, lo);
        *(uint32_t*)(g_cHi + off0) = hi;
        *(uint32_t*)(g_cLo + off0) = lo;
        size_t off1 = (rowbase + srow + 8) * D_ + col;
        pack_hl_f16(o[nt][2] * inv1, o[nt][3] * inv1, hi, lo);
        *(uint32_t*)(g_cHi + off1) = hi;
        *(uint32_t*)(g_cLo + off1) = lo;
    }
}

// ---------------------------------------------------------------------------
extern "C" void kernel_launch(void* const* d_in, const int* in_sizes, int n_in,
                              void* d_out, int out_size)
{
    const float* x  = (const float*)d_in[0];
    const float* Wq = (const float*)d_in[1];
    const float* bq = (const float*)d_in[2];
    const float* Wk = (const float*)d_in[3];
    const float* bk = (const float*)d_in[4];
    const float* Wv = (const float*)d_in[5];
    const float* bv = (const float*)d_in[6];
    const float* Wo = (const float*)d_in[7];
    const float* bo = (const float*)d_in[8];
    float* out = (float*)d_out;

    static bool attr_done = false;
    if (!attr_done) {
        cudaFuncSetAttribute(mma_gemm<0>, cudaFuncAttributeMaxDynamicSharedMemorySize, GEMM_SMEM);
        cudaFuncSetAttribute(mma_gemm<1>, cudaFuncAttributeMaxDynamicSharedMemorySize, GEMM_SMEM);
        cudaFuncSetAttribute(mma_attn,    cudaFuncAttributeMaxDynamicSharedMemorySize, ATTN_SMEM);
        attr_done = true;
    }

    // operand prep: x -> fp16 hi/lo, weights -> single fp16 transposed
    cvt_x_kernel<<<MTOT * D_ / 4 / 256, 256>>>(x);
    __half *wp, *wop;
    cudaGetSymbolAddress((void**)&wp,  g_w);
    cudaGetSymbolAddress((void**)&wop, g_wo);
    dim3 tT(32, 8);
    cvt_T_kernel<<<dim3(D_/32, DH_/32, H_), tT>>>(Wq, wp,             D_, DH_);
    cvt_T_kernel<<<dim3(D_/32, DH_/32, H_), tT>>>(Wk, wp + 1024*D_,   D_, DH_);
    cvt_T_kernel<<<dim3(D_/32, DH_/32, H_), tT>>>(Wv, wp + 2048*D_,   D_, DH_);
    cvt_T_kernel<<<dim3(D_/32, D_/32, 1),   tT>>>(Wo, wop,            D_, D_);

    // fused QKV projection (fp16 2-term) -> q hi/lo, k/v single fp16, [b*s][h*64+e]
    mma_gemm<0><<<dim3(NQKV/128, MTOT/128), 256, GEMM_SMEM>>>(bq, bk, bv, bo, out);

    // flash attention (fp16 tensor cores, single-term V) -> ctx fp16 hi/lo
    mma_attn<<<dim3(S_/128, B_*H_), 256, ATTN_SMEM>>>();

    // output projection (fp16 2-term)
    mma_gemm<1><<<dim3(D_/128, MTOT/128), 256, GEMM_SMEM>>>(bq, bk, bv, bo, out);
}

// round 16
// speedup vs baseline: 1.2798x; 1.1406x over previous
#include <cuda_runtime.h>
#include <cuda_bf16.h>
#include <cuda_fp16.h>
#include <cstdint>

// ---------------------------------------------------------------------------
// Problem constants
#define B_   2
#define S_   2048
#define D_   1024
#define H_   16
#define DH_  64
#define MTOT (B_*S_)     // 4096
#define NQKV (3*D_)      // 3072

// softmax exp2 folding: Q scaled by (1/8)*log2(e)
#define QSCALE 0.1803368801111244f

// ---------------------------------------------------------------------------
// Device-global scratch (allocation-free), all fp16
__device__ __half g_xHi[MTOT*D_];    // x split, [m][k]
__device__ __half g_xLo[MTOT*D_];
__device__ __half g_w [NQKV*D_];     // qkv weights (single fp16), [n][k], n=z*1024+h*64+e
__device__ __half g_wo[D_*D_];       // Wo^T (single fp16), [n][k]
__device__ __half g_cHi[MTOT*D_];    // ctx split, [m][k]
__device__ __half g_cLo[MTOT*D_];

// attention operands, layout [b*s][h*64+e] — ALL single fp16 now
__device__ __half g_q[MTOT*D_];      // scaled by QSCALE
__device__ __half g_k[MTOT*D_];
__device__ __half g_v[MTOT*D_];

// ---------------------------------------------------------------------------
// Baseline-PTX helpers (no sm_103a-only features)
__device__ __forceinline__ uint32_t smem_u32(const void* p) {
    uint32_t a;
    asm("{ .reg .u64 t; cvta.to.shared.u64 t, %1; cvt.u32.u64 %0, t; }" : "=r"(a) : "l"(p));
    return a;
}
__device__ __forceinline__ void ldsm4(uint32_t* r, uint32_t addr) {
    asm volatile("ldmatrix.sync.aligned.m8n8.x4.shared.b16 {%0,%1,%2,%3}, [%4];"
        : "=r"(r[0]), "=r"(r[1]), "=r"(r[2]), "=r"(r[3]) : "r"(addr));
}
__device__ __forceinline__ void ldsm4t(uint32_t* r, uint32_t addr) {
    asm volatile("ldmatrix.sync.aligned.m8n8.x4.trans.shared.b16 {%0,%1,%2,%3}, [%4];"
        : "=r"(r[0]), "=r"(r[1]), "=r"(r[2]), "=r"(r[3]) : "r"(addr));
}
__device__ __forceinline__ void mma_f16(float* c, const uint32_t* a, const uint32_t* b) {
    asm volatile("mma.sync.aligned.m16n8k16.row.col.f32.f16.f16.f32 "
        "{%0,%1,%2,%3}, {%4,%5,%6,%7}, {%8,%9}, {%0,%1,%2,%3};"
        : "+f"(c[0]), "+f"(c[1]), "+f"(c[2]), "+f"(c[3])
        : "r"(a[0]), "r"(a[1]), "r"(a[2]), "r"(a[3]), "r"(b[0]), "r"(b[1]));
}
__device__ __forceinline__ void cpasync16(uint32_t dst, const void* src) {
    asm volatile("cp.async.cg.shared.global [%0], [%1], 16;" :: "r"(dst), "l"(src) : "memory");
}
#define CP_COMMIT() asm volatile("cp.async.commit_group;" ::: "memory")
#define CP_WAIT(n)  asm volatile("cp.async.wait_group %0;" :: "n"(n) : "memory")

__device__ __forceinline__ float ex2(float x) {
    float y;
    asm("ex2.approx.f32 %0, %1;" : "=f"(y) : "f"(x));
    return y;
}

// pack two fp32 into f16x2 hi-word and lo-word (x -> low 16 bits)
__device__ __forceinline__ void pack_hl_f16(float x, float y, uint32_t& hi, uint32_t& lo) {
    __half hx = __float2half_rn(x), hy = __float2half_rn(y);
    __half lx = __float2half_rn(x - __half2float(hx));
    __half ly = __float2half_rn(y - __half2float(hy));
    __half2 h2 = __halves2half2(hx, hy);
    __half2 l2 = __halves2half2(lx, ly);
    hi = *(uint32_t*)&h2;
    lo = *(uint32_t*)&l2;
}
__device__ __forceinline__ uint32_t pack_f16(float x, float y) {
    __half2 h2 = __floats2half2_rn(x, y);
    return *(uint32_t*)&h2;
}

// ---------------------------------------------------------------------------
// Conversion kernels
__global__ __launch_bounds__(256) void cvt_x_kernel(const float* __restrict__ x) {
    int i = blockIdx.x * 256 + threadIdx.x;
    float4 v = ((const float4*)x)[i];
    uint32_t h0, l0, h1, l1;
    pack_hl_f16(v.x, v.y, h0, l0);
    pack_hl_f16(v.z, v.w, h1, l1);
    ((uint32_t*)g_xHi)[2*i]   = h0;
    ((uint32_t*)g_xHi)[2*i+1] = h1;
    ((uint32_t*)g_xLo)[2*i]   = l0;
    ((uint32_t*)g_xLo)[2*i+1] = l1;
}

// QKV weight transpose-convert, all three weights in ONE launch.
// z = 0..47: weight = z/16 (Wq/Wk/Wv), head slab = z%16. [1024][64] -> [64][1024] fp16.
__global__ __launch_bounds__(256)
void cvt_T3_kernel(const float* __restrict__ Wq, const float* __restrict__ Wk,
                   const float* __restrict__ Wv)
{
    __shared__ float tb[32][33];
    const int z = blockIdx.z, wsel = z >> 4, slab = z & 15;
    const float* src = ((wsel == 0) ? Wq : (wsel == 1) ? Wk : Wv) + (size_t)slab * D_ * DH_;
    __half* dst = g_w + (size_t)z * (D_ * DH_);   // z*65536
    const int r0 = blockIdx.x * 32, c0 = blockIdx.y * 32;
    const int tx = threadIdx.x, ty = threadIdx.y;   // (32, 8)
#pragma unroll
    for (int i = 0; i < 4; i++)
        tb[ty + i*8][tx] = src[(size_t)(r0 + ty + i*8) * DH_ + (c0 + tx)];
    __syncthreads();
#pragma unroll
    for (int i = 0; i < 4; i++)
        dst[(size_t)(c0 + ty + i*8) * D_ + (r0 + tx)] = __float2half_rn(tb[tx][ty + i*8]);
}

// Wo transpose-convert: [1024][1024] -> [1024][1024]^T fp16
__global__ __launch_bounds__(256)
void cvt_To_kernel(const float* __restrict__ Wo)
{
    __shared__ float tb[32][33];
    const int r0 = blockIdx.x * 32, c0 = blockIdx.y * 32;
    const int tx = threadIdx.x, ty = threadIdx.y;
#pragma unroll
    for (int i = 0; i < 4; i++)
        tb[ty + i*8][tx] = Wo[(size_t)(r0 + ty + i*8) * D_ + (c0 + tx)];
    __syncthreads();
#pragma unroll
    for (int i = 0; i < 4; i++)
        g_wo[(size_t)(c0 + ty + i*8) * D_ + (r0 + tx)] = __float2half_rn(tb[tx][ty + i*8]);
}

// ---------------------------------------------------------------------------
// mma.sync GEMM: C[128x128] per CTA, K=1024 in 16 chunks of 64.
// fp16 2-term: (Ah + Al) x B(single fp16). Stage = [Ah][Al][B], 3 tiles.
// Inner loop issues the aH pass then the aL pass: consecutive MMAs always hit
// distinct accumulators (RAW reuse distance 8).
#define RB     144
#define GTILE  (128*RB)                 // 18432
#define GEMM_SMEM (2*3*GTILE)           // 110592

template <int MODE>
__global__ __launch_bounds__(256, 2)
void mma_gemm(const float* __restrict__ bq, const float* __restrict__ bk,
              const float* __restrict__ bv, const float* __restrict__ bo,
              float* __restrict__ out)
{
    extern __shared__ char smem[];
    const uint32_t sb = smem_u32(smem);
    const int tid = threadIdx.x, w = tid >> 5, t = tid & 31;
    const int m0 = blockIdx.y * 128, n0 = blockIdx.x * 128;
    const int mw = (w & 3) * 32, nw = (w >> 2) * 64;

    const __half* Ah = (MODE == 0) ? g_xHi : g_cHi;
    const __half* Al = (MODE == 0) ? g_xLo : g_cLo;
    const __half* Bw = (MODE == 0) ? g_w   : g_wo;

    float c[2][8][4];
#pragma unroll
    for (int i = 0; i < 2; i++)
#pragma unroll
        for (int j = 0; j < 8; j++)
#pragma unroll
            for (int q = 0; q < 4; q++) c[i][j][q] = 0.f;

    const int u  = tid & 7;
    const int r0 = tid >> 3;

    // ---- prologue: load chunk 0 into stage 0
#pragma unroll
    for (int p = 0; p < 4; p++) {
        int row = r0 + p * 32;
        uint32_t d = sb + row * RB + u * 16;
        cpasync16(d,             Ah + (size_t)(m0 + row) * D_ + u * 8);
        cpasync16(d + GTILE,     Al + (size_t)(m0 + row) * D_ + u * 8);
        cpasync16(d + 2*GTILE,   Bw + (size_t)(n0 + row) * D_ + u * 8);
    }
    CP_COMMIT();

    for (int kb = 0; kb < 16; kb++) {
        if (kb < 15) {
            const int st = (kb + 1) & 1;
            const int ko = (kb + 1) * 64;
#pragma unroll
            for (int p = 0; p < 4; p++) {
                int row = r0 + p * 32;
                uint32_t d = sb + st * 3 * GTILE + row * RB + u * 16;
                cpasync16(d,           Ah + (size_t)(m0 + row) * D_ + ko + u * 8);
                cpasync16(d + GTILE,   Al + (size_t)(m0 + row) * D_ + ko + u * 8);
                cpasync16(d + 2*GTILE, Bw + (size_t)(n0 + row) * D_ + ko + u * 8);
            }
            CP_COMMIT();
            CP_WAIT(1);
        } else {
            CP_WAIT(0);
        }
        __syncthreads();

        const uint32_t base = sb + (kb & 1) * 3 * GTILE;
#pragma unroll
        for (int ks = 0; ks < 4; ks++) {
            uint32_t aH[2][4], aL[2][4], bF[4][4];
#pragma unroll
            for (int mt = 0; mt < 2; mt++) {
                uint32_t ad = base + (mw + 16*mt + (t & 15)) * RB + ks * 32 + (t >> 4) * 16;
                ldsm4(aH[mt], ad);
                ldsm4(aL[mt], ad + GTILE);
            }
#pragma unroll
            for (int np = 0; np < 4; np++) {
                uint32_t ad = base + 2*GTILE
                            + (nw + np*16 + ((t >> 4) << 3) + (t & 7)) * RB
                            + ks * 32 + ((t >> 3) & 1) * 16;
                ldsm4(bF[np], ad);
            }
            // aH pass: 16 MMAs, all distinct accumulators
#pragma unroll
            for (int np = 0; np < 4; np++)
#pragma unroll
                for (int mt = 0; mt < 2; mt++) {
                    mma_f16(c[mt][2*np],   aH[mt], bF[np]);
                    mma_f16(c[mt][2*np+1], aH[mt], bF[np] + 2);
                }
            // aL pass
#pragma unroll
            for (int np = 0; np < 4; np++)
#pragma unroll
                for (int mt = 0; mt < 2; mt++) {
                    mma_f16(c[mt][2*np],   aL[mt], bF[np]);
                    mma_f16(c[mt][2*np+1], aL[mt], bF[np] + 2);
                }
        }
        __syncthreads();
    }

    // ---- epilogue (coalesced 16B segments per quad)
    const int g = t >> 2, i2 = (t & 3) * 2;
    if (MODE == 0) {
        const int z = n0 >> 10;
        const float scale = (z == 0) ? QSCALE : 1.0f;   // log2e folded into Q
        const float* bias = (z == 0) ? bq : (z == 1) ? bk : bv;
        __half* dst = (z == 0) ? g_q : (z == 1) ? g_k : g_v;
        const int nin0 = n0 & 1023;               // column base within [m][1024] layout
#pragma unroll
        for (int mt = 0; mt < 2; mt++) {
#pragma unroll
            for (int rr = 0; rr < 2; rr++) {
                const int m = m0 + mw + 16*mt + g + rr*8;
#pragma unroll
                for (int nt = 0; nt < 8; nt++) {
                    const int col = nw + nt*8 + i2;
                    const int nin = nin0 + col;
                    float v0 = (c[mt][nt][rr*2+0] + bias[nin])   * scale;
                    float v1 = (c[mt][nt][rr*2+1] + bias[nin+1]) * scale;
                    *(uint32_t*)(dst + (size_t)m * D_ + nin) = pack_f16(v0, v1);
                }
            }
        }
    } else {
#pragma unroll
        for (int mt = 0; mt < 2; mt++) {
#pragma unroll
            for (int rr = 0; rr < 2; rr++) {
                const int m = m0 + mw + 16*mt + g + rr*8;
#pragma unroll
                for (int nt = 0; nt < 8; nt++) {
                    const int col = n0 + nw + nt*8 + i2;
                    float2 v;
                    v.x = c[mt][nt][rr*2+0] + bo[col];
                    v.y = c[mt][nt][rr*2+1] + bo[col+1];
                    *(float2*)(out + (size_t)m * D_ + col) = v;
                }
            }
        }
    }
}

// ---------------------------------------------------------------------------
// mma.sync flash attention, all-fp16 single-term, K/V double-buffered,
// Q hoisted to regs. 128 q-rows per CTA, 8 warps x 16 rows, 64-key blocks.
// QK^T: Q x K (1 MMA). PV: P x V (1 MMA). 64 HMMA per warp-iter.
// smem: Q [128][72] + 2 stages x (K/V [64][72]) = 55296 B
#define QT    (128*RB)     // 18432
#define KT    (64*RB)      // 9216
#define KVST  (2*KT)       // 18432
#define ATTN_SMEM (QT + 2*KVST)

__global__ __launch_bounds__(256, 2)
void mma_attn()
{
    extern __shared__ char smem[];
    const uint32_t sb = smem_u32(smem);
    const int tid = threadIdx.x, w = tid >> 5, t = tid & 31;
    const int qb = blockIdx.x, bh = blockIdx.y;
    const int batch = bh >> 4, h = bh & 15;
    const size_t rowbase = (size_t)batch * S_;      // global row = rowbase + s
    const int hcol = h * DH_;                       // column offset within 1024-wide row

    const uint32_t QH = sb;
    const uint32_t KV0 = sb + QT;       // stage s at KV0 + s*KVST: [K][V]

    const int u = tid & 7, r0 = tid >> 3;

    // ---- prologue group 1: Q tile
#pragma unroll
    for (int p = 0; p < 4; p++) {
        int row = r0 + p * 32;
        size_t src = (rowbase + qb * 128 + row) * D_ + hcol + u * 8;
        cpasync16(QH + row * RB + u * 16, g_q + src);
    }
    CP_COMMIT();
    // ---- prologue group 2: K/V block 0
#pragma unroll
    for (int p = 0; p < 2; p++) {
        int row = r0 + p * 32;
        size_t src = (rowbase + row) * D_ + hcol + u * 8;
        uint32_t d = KV0 + row * RB + u * 16;
        cpasync16(d,          g_k + src);
        cpasync16(d + KT,     g_v + src);
    }
    CP_COMMIT();

    // ---- hoist Q fragments into registers (loop-invariant)
    CP_WAIT(1);          // Q group done (KV0 may still be in flight)
    __syncthreads();
    uint32_t qa[4][4];
#pragma unroll
    for (int ks = 0; ks < 4; ks++)
        ldsm4(qa[ks], QH + (w * 16 + (t & 15)) * RB + ks * 32 + (t >> 4) * 16);

    float o[8][4];
#pragma unroll
    for (int j = 0; j < 8; j++)
#pragma unroll
        for (int q = 0; q < 4; q++) o[j][q] = 0.f;
    float mr0 = -1e30f, mr1 = -1e30f, lr0 = 0.f, lr1 = 0.f;

    for (int kb = 0; kb < 32; kb++) {
        if (kb < 31) {
            const uint32_t st = KV0 + ((kb + 1) & 1) * KVST;
#pragma unroll
            for (int p = 0; p < 2; p++) {
                int row = r0 + p * 32;
                size_t src = (rowbase + (kb + 1) * 64 + row) * D_ + hcol + u * 8;
                uint32_t d = st + row * RB + u * 16;
                cpasync16(d,          g_k + src);
                cpasync16(d + KT,     g_v + src);
            }
            CP_COMMIT();
            CP_WAIT(1);
        } else {
            CP_WAIT(0);
        }
        __syncthreads();

        const uint32_t KH = KV0 + (kb & 1) * KVST;
        const uint32_t VH = KH + KT;

        // ---- S(log2 domain) = Q K^T, single term; accumulators spread per pass
        float s[8][4];
#pragma unroll
        for (int j = 0; j < 8; j++)
#pragma unroll
            for (int q = 0; q < 4; q++) s[j][q] = 0.f;
#pragma unroll
        for (int ks = 0; ks < 4; ks++) {
            uint32_t bF[4][4];
#pragma unroll
            for (int np = 0; np < 4; np++) {
                uint32_t bd = KH + (np*16 + ((t >> 4) << 3) + (t & 7)) * RB
                            + ks * 32 + ((t >> 3) & 1) * 16;
                ldsm4(bF[np], bd);
            }
#pragma unroll
            for (int np = 0; np < 4; np++) {
                mma_f16(s[2*np],   qa[ks], bF[np]);
                mma_f16(s[2*np+1], qa[ks], bF[np] + 2);
            }
        }

        // ---- online softmax in log2 domain (rows g and g+8, row within warp)
        float rmax0 = -1e30f, rmax1 = -1e30f;
#pragma unroll
        for (int j = 0; j < 8; j++) {
            rmax0 = fmaxf(rmax0, fmaxf(s[j][0], s[j][1]));
            rmax1 = fmaxf(rmax1, fmaxf(s[j][2], s[j][3]));
        }
#pragma unroll
        for (int off = 1; off <= 2; off <<= 1) {
            rmax0 = fmaxf(rmax0, __shfl_xor_sync(0xffffffffu, rmax0, off));
            rmax1 = fmaxf(rmax1, __shfl_xor_sync(0xffffffffu, rmax1, off));
        }
        float mn0 = fmaxf(mr0, rmax0), mn1 = fmaxf(mr1, rmax1);
        float corr0 = ex2(mr0 - mn0), corr1 = ex2(mr1 - mn1);
        mr0 = mn0; mr1 = mn1;

        float sum0 = 0.f, sum1 = 0.f;
#pragma unroll
        for (int j = 0; j < 8; j++) {
            s[j][0] = ex2(s[j][0] - mn0);
            s[j][1] = ex2(s[j][1] - mn0);
            s[j][2] = ex2(s[j][2] - mn1);
            s[j][3] = ex2(s[j][3] - mn1);
            sum0 += s[j][0] + s[j][1];
            sum1 += s[j][2] + s[j][3];
        }
#pragma unroll
        for (int off = 1; off <= 2; off <<= 1) {
            sum0 += __shfl_xor_sync(0xffffffffu, sum0, off);
            sum1 += __shfl_xor_sync(0xffffffffu, sum1, off);
        }
        lr0 = lr0 * corr0 + sum0;
        lr1 = lr1 * corr1 + sum1;
#pragma unroll
        for (int j = 0; j < 8; j++) {
            o[j][0] *= corr0; o[j][1] *= corr0;
            o[j][2] *= corr1; o[j][3] *= corr1;
        }

        // ---- pack P (single fp16) into PV A-fragments
        uint32_t pH[4][4];
#pragma unroll
        for (int kk = 0; kk < 4; kk++) {
            pH[kk][0] = pack_f16(s[2*kk][0],   s[2*kk][1]);
            pH[kk][1] = pack_f16(s[2*kk][2],   s[2*kk][3]);
            pH[kk][2] = pack_f16(s[2*kk+1][0], s[2*kk+1][1]);
            pH[kk][3] = pack_f16(s[2*kk+1][2], s[2*kk+1][3]);
        }

        // ---- O += P * V, V via ldmatrix.trans (single term)
#pragma unroll
        for (int kk = 0; kk < 4; kk++) {
#pragma unroll
            for (int jp = 0; jp < 4; jp++) {
                uint32_t vF[4];
                uint32_t vd = VH + (kk*16 + (t & 7) + (((t >> 3) & 1) << 3)) * RB
                            + jp * 32 + ((t >> 4) << 4);
                ldsm4t(vF, vd);
                mma_f16(o[2*jp],   pH[kk], vF);
                mma_f16(o[2*jp+1], pH[kk], vF + 2);
            }
        }

        __syncthreads();   // stage (kb&1) fully consumed before iter kb+1 refills it
    }

    // ---- epilogue: ctx[b*S+s][h*64+e] as fp16 hi/lo
    const float inv0 = 1.0f / lr0, inv1 = 1.0f / lr1;
    const int srow = qb * 128 + w * 16 + (t >> 2);
    const int i2 = (t & 3) * 2;
#pragma unroll
    for (int nt = 0; nt < 8; nt++) {
        const int col = hcol + nt * 8 + i2;
        uint32_t hi, lo;
        size_t off0 = (rowbase + srow) * D_ + col;
        pack_hl_f16(o[nt][0] * inv0, o[nt][1] * inv0, hi, lo);
        *(uint32_t*)(g_cHi + off0) = hi;
        *(uint32_t*)(g_cLo + off0) = lo;
        size_t off1 = (rowbase + srow + 8) * D_ + col;
        pack_hl_f16(o[nt][2] * inv1, o[nt][3] * inv1, hi, lo);
        *(uint32_t*)(g_cHi + off1) = hi;
        *(uint32_t*)(g_cLo + off1) = lo;
    }
}

// ---------------------------------------------------------------------------
extern "C" void kernel_launch(void* const* d_in, const int* in_sizes, int n_in,
                              void* d_out, int out_size)
{
    const float* x  = (const float*)d_in[0];
    const float* Wq = (const float*)d_in[1];
    const float* bq = (const float*)d_in[2];
    const float* Wk = (const float*)d_in[3];
    const float* bk = (const float*)d_in[4];
    const float* Wv = (const float*)d_in[5];
    const float* bv = (const float*)d_in[6];
    const float* Wo = (const float*)d_in[7];
    const float* bo = (const float*)d_in[8];
    float* out = (float*)d_out;

    static bool attr_done = false;
    if (!attr_done) {
        cudaFuncSetAttribute(mma_gemm<0>, cudaFuncAttributeMaxDynamicSharedMemorySize, GEMM_SMEM);
        cudaFuncSetAttribute(mma_gemm<1>, cudaFuncAttributeMaxDynamicSharedMemorySize, GEMM_SMEM);
        cudaFuncSetAttribute(mma_attn,    cudaFuncAttributeMaxDynamicSharedMemorySize, ATTN_SMEM);
        attr_done = true;
    }

    // operand prep: x -> fp16 hi/lo; weights -> single fp16 transposed (2 launches)
    cvt_x_kernel<<<MTOT * D_ / 4 / 256, 256>>>(x);
    dim3 tT(32, 8);
    cvt_T3_kernel<<<dim3(D_/32, DH_/32, 3*H_), tT>>>(Wq, Wk, Wv);
    cvt_To_kernel<<<dim3(D_/32, D_/32),        tT>>>(Wo);

    // fused QKV projection (fp16 2-term GEMM) -> q/k/v single fp16 [b*s][h*64+e]
    mma_gemm<0><<<dim3(NQKV/128, MTOT/128), 256, GEMM_SMEM>>>(bq, bk, bv, bo, out);

    // flash attention (all-fp16 tensor cores) -> ctx fp16 hi/lo
    mma_attn<<<dim3(S_/128, B_*H_), 256, ATTN_SMEM>>>();

    // output projection (fp16 2-term)
    mma_gemm<1><<<dim3(D_/128, MTOT/128), 256, GEMM_SMEM>>>(bq, bk, bv, bo, out);
}

// round 17
// speedup vs baseline: 1.4250x; 1.1135x over previous
#include <cuda_runtime.h>
#include <cuda_bf16.h>
#include <cuda_fp16.h>
#include <cstdint>

// ---------------------------------------------------------------------------
// Problem constants
#define B_   2
#define S_   2048
#define D_   1024
#define H_   16
#define DH_  64
#define MTOT (B_*S_)     // 4096
#define NQKV (3*D_)      // 3072

// softmax exp2 folding: Q scaled by (1/8)*log2(e)
#define QSCALE 0.1803368801111244f

// ---------------------------------------------------------------------------
// Device-global scratch (allocation-free), all fp16
__device__ __half g_xHi[MTOT*D_];    // x split, [m][k]
__device__ __half g_xLo[MTOT*D_];
__device__ __half g_w [NQKV*D_];     // qkv weights (single fp16), [n][k], n=z*1024+h*64+e
__device__ __half g_wo[D_*D_];       // Wo^T (single fp16), [n][k]
__device__ __half g_cHi[MTOT*D_];    // ctx split, [m][k]
__device__ __half g_cLo[MTOT*D_];

// attention operands, layout [b*s][h*64+e] — all single fp16
__device__ __half g_q[MTOT*D_];      // scaled by QSCALE
__device__ __half g_k[MTOT*D_];
__device__ __half g_v[MTOT*D_];

// ---------------------------------------------------------------------------
// Baseline-PTX helpers (no sm_103a-only features)
__device__ __forceinline__ uint32_t smem_u32(const void* p) {
    uint32_t a;
    asm("{ .reg .u64 t; cvta.to.shared.u64 t, %1; cvt.u32.u64 %0, t; }" : "=r"(a) : "l"(p));
    return a;
}
__device__ __forceinline__ void ldsm4(uint32_t* r, uint32_t addr) {
    asm volatile("ldmatrix.sync.aligned.m8n8.x4.shared.b16 {%0,%1,%2,%3}, [%4];"
        : "=r"(r[0]), "=r"(r[1]), "=r"(r[2]), "=r"(r[3]) : "r"(addr));
}
__device__ __forceinline__ void ldsm4t(uint32_t* r, uint32_t addr) {
    asm volatile("ldmatrix.sync.aligned.m8n8.x4.trans.shared.b16 {%0,%1,%2,%3}, [%4];"
        : "=r"(r[0]), "=r"(r[1]), "=r"(r[2]), "=r"(r[3]) : "r"(addr));
}
__device__ __forceinline__ void mma_f16(float* c, const uint32_t* a, const uint32_t* b) {
    asm volatile("mma.sync.aligned.m16n8k16.row.col.f32.f16.f16.f32 "
        "{%0,%1,%2,%3}, {%4,%5,%6,%7}, {%8,%9}, {%0,%1,%2,%3};"
        : "+f"(c[0]), "+f"(c[1]), "+f"(c[2]), "+f"(c[3])
        : "r"(a[0]), "r"(a[1]), "r"(a[2]), "r"(a[3]), "r"(b[0]), "r"(b[1]));
}
__device__ __forceinline__ void cpasync16(uint32_t dst, const void* src) {
    asm volatile("cp.async.cg.shared.global [%0], [%1], 16;" :: "r"(dst), "l"(src) : "memory");
}
#define CP_COMMIT() asm volatile("cp.async.commit_group;" ::: "memory")
#define CP_WAIT(n)  asm volatile("cp.async.wait_group %0;" :: "n"(n) : "memory")

__device__ __forceinline__ float ex2(float x) {
    float y;
    asm("ex2.approx.f32 %0, %1;" : "=f"(y) : "f"(x));
    return y;
}

// pack two fp32 into f16x2 hi-word and lo-word (x -> low 16 bits)
__device__ __forceinline__ void pack_hl_f16(float x, float y, uint32_t& hi, uint32_t& lo) {
    __half hx = __float2half_rn(x), hy = __float2half_rn(y);
    __half lx = __float2half_rn(x - __half2float(hx));
    __half ly = __float2half_rn(y - __half2float(hy));
    __half2 h2 = __halves2half2(hx, hy);
    __half2 l2 = __halves2half2(lx, ly);
    hi = *(uint32_t*)&h2;
    lo = *(uint32_t*)&l2;
}
__device__ __forceinline__ uint32_t pack_f16(float x, float y) {
    __half2 h2 = __floats2half2_rn(x, y);
    return *(uint32_t*)&h2;
}

// ---------------------------------------------------------------------------
// Conversion kernels
__global__ __launch_bounds__(256) void cvt_x_kernel(const float* __restrict__ x) {
    int i = blockIdx.x * 256 + threadIdx.x;
    float4 v = ((const float4*)x)[i];
    uint32_t h0, l0, h1, l1;
    pack_hl_f16(v.x, v.y, h0, l0);
    pack_hl_f16(v.z, v.w, h1, l1);
    ((uint32_t*)g_xHi)[2*i]   = h0;
    ((uint32_t*)g_xHi)[2*i+1] = h1;
    ((uint32_t*)g_xLo)[2*i]   = l0;
    ((uint32_t*)g_xLo)[2*i+1] = l1;
}

// QKV weight transpose-convert, all three weights in ONE launch.
__global__ __launch_bounds__(256)
void cvt_T3_kernel(const float* __restrict__ Wq, const float* __restrict__ Wk,
                   const float* __restrict__ Wv)
{
    __shared__ float tb[32][33];
    const int z = blockIdx.z, wsel = z >> 4, slab = z & 15;
    const float* src = ((wsel == 0) ? Wq : (wsel == 1) ? Wk : Wv) + (size_t)slab * D_ * DH_;
    __half* dst = g_w + (size_t)z * (D_ * DH_);
    const int r0 = blockIdx.x * 32, c0 = blockIdx.y * 32;
    const int tx = threadIdx.x, ty = threadIdx.y;
#pragma unroll
    for (int i = 0; i < 4; i++)
        tb[ty + i*8][tx] = src[(size_t)(r0 + ty + i*8) * DH_ + (c0 + tx)];
    __syncthreads();
#pragma unroll
    for (int i = 0; i < 4; i++)
        dst[(size_t)(c0 + ty + i*8) * D_ + (r0 + tx)] = __float2half_rn(tb[tx][ty + i*8]);
}

// Wo transpose-convert: [1024][1024] -> transposed fp16
__global__ __launch_bounds__(256)
void cvt_To_kernel(const float* __restrict__ Wo)
{
    __shared__ float tb[32][33];
    const int r0 = blockIdx.x * 32, c0 = blockIdx.y * 32;
    const int tx = threadIdx.x, ty = threadIdx.y;
#pragma unroll
    for (int i = 0; i < 4; i++)
        tb[ty + i*8][tx] = Wo[(size_t)(r0 + ty + i*8) * D_ + (c0 + tx)];
    __syncthreads();
#pragma unroll
    for (int i = 0; i < 4; i++)
        g_wo[(size_t)(c0 + ty + i*8) * D_ + (r0 + tx)] = __float2half_rn(tb[tx][ty + i*8]);
}

// ---------------------------------------------------------------------------
// mma.sync GEMM: C[128x128] per CTA, K=1024 in 16 chunks of 64.
// A 2-term (Ah+Al) x B — except qkv K/V output columns (z>=1), which use Ah only
// (their outputs are rounded to single fp16 anyway; lo-term is wasted there).
#define RB     144
#define GTILE  (128*RB)                 // 18432
#define GEMM_SMEM (2*3*GTILE)           // 110592

template <int MODE>
__global__ __launch_bounds__(256, 2)
void mma_gemm(const float* __restrict__ bq, const float* __restrict__ bk,
              const float* __restrict__ bv, const float* __restrict__ bo,
              float* __restrict__ out)
{
    extern __shared__ char smem[];
    const uint32_t sb = smem_u32(smem);
    const int tid = threadIdx.x, w = tid >> 5, t = tid & 31;
    const int m0 = blockIdx.y * 128, n0 = blockIdx.x * 128;
    const int mw = (w & 3) * 32, nw = (w >> 2) * 64;
    const bool twoTerm = (MODE == 1) || (n0 < 1024);   // Q third + proj: 2-term

    const __half* Ah = (MODE == 0) ? g_xHi : g_cHi;
    const __half* Al = (MODE == 0) ? g_xLo : g_cLo;
    const __half* Bw = (MODE == 0) ? g_w   : g_wo;

    float c[2][8][4];
#pragma unroll
    for (int i = 0; i < 2; i++)
#pragma unroll
        for (int j = 0; j < 8; j++)
#pragma unroll
            for (int q = 0; q < 4; q++) c[i][j][q] = 0.f;

    const int u  = tid & 7;
    const int r0 = tid >> 3;

    // ---- prologue: load chunk 0 into stage 0
#pragma unroll
    for (int p = 0; p < 4; p++) {
        int row = r0 + p * 32;
        uint32_t d = sb + row * RB + u * 16;
        cpasync16(d,           Ah + (size_t)(m0 + row) * D_ + u * 8);
        if (twoTerm)
            cpasync16(d + GTILE, Al + (size_t)(m0 + row) * D_ + u * 8);
        cpasync16(d + 2*GTILE, Bw + (size_t)(n0 + row) * D_ + u * 8);
    }
    CP_COMMIT();

    for (int kb = 0; kb < 16; kb++) {
        if (kb < 15) {
            const int st = (kb + 1) & 1;
            const int ko = (kb + 1) * 64;
#pragma unroll
            for (int p = 0; p < 4; p++) {
                int row = r0 + p * 32;
                uint32_t d = sb + st * 3 * GTILE + row * RB + u * 16;
                cpasync16(d,           Ah + (size_t)(m0 + row) * D_ + ko + u * 8);
                if (twoTerm)
                    cpasync16(d + GTILE, Al + (size_t)(m0 + row) * D_ + ko + u * 8);
                cpasync16(d + 2*GTILE, Bw + (size_t)(n0 + row) * D_ + ko + u * 8);
            }
            CP_COMMIT();
            CP_WAIT(1);
        } else {
            CP_WAIT(0);
        }
        __syncthreads();

        const uint32_t base = sb + (kb & 1) * 3 * GTILE;
#pragma unroll
        for (int ks = 0; ks < 4; ks++) {
            uint32_t aH[2][4], aL[2][4], bF[4][4];
#pragma unroll
            for (int mt = 0; mt < 2; mt++) {
                uint32_t ad = base + (mw + 16*mt + (t & 15)) * RB + ks * 32 + (t >> 4) * 16;
                ldsm4(aH[mt], ad);
                if (twoTerm) ldsm4(aL[mt], ad + GTILE);
            }
#pragma unroll
            for (int np = 0; np < 4; np++) {
                uint32_t ad = base + 2*GTILE
                            + (nw + np*16 + ((t >> 4) << 3) + (t & 7)) * RB
                            + ks * 32 + ((t >> 3) & 1) * 16;
                ldsm4(bF[np], ad);
            }
            // aH pass: distinct accumulators back-to-back
#pragma unroll
            for (int np = 0; np < 4; np++)
#pragma unroll
                for (int mt = 0; mt < 2; mt++) {
                    mma_f16(c[mt][2*np],   aH[mt], bF[np]);
                    mma_f16(c[mt][2*np+1], aH[mt], bF[np] + 2);
                }
            if (twoTerm) {
#pragma unroll
                for (int np = 0; np < 4; np++)
#pragma unroll
                    for (int mt = 0; mt < 2; mt++) {
                        mma_f16(c[mt][2*np],   aL[mt], bF[np]);
                        mma_f16(c[mt][2*np+1], aL[mt], bF[np] + 2);
                    }
            }
        }
        __syncthreads();
    }

    // ---- epilogue (coalesced 16B segments per quad)
    const int g = t >> 2, i2 = (t & 3) * 2;
    if (MODE == 0) {
        const int z = n0 >> 10;
        const float scale = (z == 0) ? QSCALE : 1.0f;
        const float* bias = (z == 0) ? bq : (z == 1) ? bk : bv;
        __half* dst = (z == 0) ? g_q : (z == 1) ? g_k : g_v;
        const int nin0 = n0 & 1023;
#pragma unroll
        for (int mt = 0; mt < 2; mt++) {
#pragma unroll
            for (int rr = 0; rr < 2; rr++) {
                const int m = m0 + mw + 16*mt + g + rr*8;
#pragma unroll
                for (int nt = 0; nt < 8; nt++) {
                    const int col = nw + nt*8 + i2;
                    const int nin = nin0 + col;
                    float v0 = (c[mt][nt][rr*2+0] + bias[nin])   * scale;
                    float v1 = (c[mt][nt][rr*2+1] + bias[nin+1]) * scale;
                    *(uint32_t*)(dst + (size_t)m * D_ + nin) = pack_f16(v0, v1);
                }
            }
        }
    } else {
#pragma unroll
        for (int mt = 0; mt < 2; mt++) {
#pragma unroll
            for (int rr = 0; rr < 2; rr++) {
                const int m = m0 + mw + 16*mt + g + rr*8;
#pragma unroll
                for (int nt = 0; nt < 8; nt++) {
                    const int col = n0 + nw + nt*8 + i2;
                    float2 v;
                    v.x = c[mt][nt][rr*2+0] + bo[col];
                    v.y = c[mt][nt][rr*2+1] + bo[col+1];
                    *(float2*)(out + (size_t)m * D_ + col) = v;
                }
            }
        }
    }
}

// ---------------------------------------------------------------------------
// mma.sync flash attention, all-fp16, 3-stage KV ring, ONE barrier/iteration.
// 128 q-rows per CTA, 8 warps x 16 rows, 64-key blocks, Q hoisted to regs.
// Ring safety: sync sits before the load-issue, so window kb writes stage
// (kb+1)%3 while the laggiest warp (window kb-1) reads (kb-1)%3 — distinct mod 3.
// smem: Q [128][72] + 3 stages x (K/V [64][72]) = 73728 B; 2 CTAs/SM.
#define QT    (128*RB)     // 18432
#define KT    (64*RB)      // 9216
#define KVST  (2*KT)       // 18432
#define ATTN_SMEM (QT + 3*KVST)

__global__ __launch_bounds__(256, 2)
void mma_attn()
{
    extern __shared__ char smem[];
    const uint32_t sb = smem_u32(smem);
    const int tid = threadIdx.x, w = tid >> 5, t = tid & 31;
    const int qb = blockIdx.x, bh = blockIdx.y;
    const int batch = bh >> 4, h = bh & 15;
    const size_t rowbase = (size_t)batch * S_;
    const int hcol = h * DH_;

    const uint32_t QH = sb;
    const uint32_t KV0 = sb + QT;       // stage s at KV0 + s*KVST: [K][V]

    const int u = tid & 7, r0 = tid >> 3;

    // ---- prologue group 1: Q tile
#pragma unroll
    for (int p = 0; p < 4; p++) {
        int row = r0 + p * 32;
        size_t src = (rowbase + qb * 128 + row) * D_ + hcol + u * 8;
        cpasync16(QH + row * RB + u * 16, g_q + src);
    }
    CP_COMMIT();
    // ---- prologue group 2: K/V block 0 into stage 0
#pragma unroll
    for (int p = 0; p < 2; p++) {
        int row = r0 + p * 32;
        size_t src = (rowbase + row) * D_ + hcol + u * 8;
        uint32_t d = KV0 + row * RB + u * 16;
        cpasync16(d,          g_k + src);
        cpasync16(d + KT,     g_v + src);
    }
    CP_COMMIT();

    // ---- hoist Q fragments into registers
    CP_WAIT(1);          // Q group arrived (stage-0 group may be in flight)
    __syncthreads();
    uint32_t qa[4][4];
#pragma unroll
    for (int ks = 0; ks < 4; ks++)
        ldsm4(qa[ks], QH + (w * 16 + (t & 15)) * RB + ks * 32 + (t >> 4) * 16);

    float o[8][4];
#pragma unroll
    for (int j = 0; j < 8; j++)
#pragma unroll
        for (int q = 0; q < 4; q++) o[j][q] = 0.f;
    float mr0 = -1e30f, mr1 = -1e30f, lr0 = 0.f, lr1 = 0.f;

    int cur = 0, nxt = 1;               // ring indices kb%3, (kb+1)%3
    for (int kb = 0; kb < 32; kb++) {
        __syncthreads();                // ONE barrier per iteration (see header)
        if (kb < 31) {
            const uint32_t st = KV0 + nxt * KVST;
#pragma unroll
            for (int p = 0; p < 2; p++) {
                int row = r0 + p * 32;
                size_t src = (rowbase + (kb + 1) * 64 + row) * D_ + hcol + u * 8;
                uint32_t d = st + row * RB + u * 16;
                cpasync16(d,          g_k + src);
                cpasync16(d + KT,     g_v + src);
            }
            CP_COMMIT();
            CP_WAIT(1);                 // stage kb arrived
        } else {
            CP_WAIT(0);
        }

        const uint32_t KH = KV0 + cur * KVST;
        const uint32_t VH = KH + KT;

        // ---- S(log2 domain) = Q K^T
        float s[8][4];
#pragma unroll
        for (int j = 0; j < 8; j++)
#pragma unroll
            for (int q = 0; q < 4; q++) s[j][q] = 0.f;
#pragma unroll
        for (int ks = 0; ks < 4; ks++) {
            uint32_t bF[4][4];
#pragma unroll
            for (int np = 0; np < 4; np++) {
                uint32_t bd = KH + (np*16 + ((t >> 4) << 3) + (t & 7)) * RB
                            + ks * 32 + ((t >> 3) & 1) * 16;
                ldsm4(bF[np], bd);
            }
#pragma unroll
            for (int np = 0; np < 4; np++) {
                mma_f16(s[2*np],   qa[ks], bF[np]);
                mma_f16(s[2*np+1], qa[ks], bF[np] + 2);
            }
        }

        // ---- online softmax in log2 domain
        float rmax0 = -1e30f, rmax1 = -1e30f;
#pragma unroll
        for (int j = 0; j < 8; j++) {
            rmax0 = fmaxf(rmax0, fmaxf(s[j][0], s[j][1]));
            rmax1 = fmaxf(rmax1, fmaxf(s[j][2], s[j][3]));
        }
#pragma unroll
        for (int off = 1; off <= 2; off <<= 1) {
            rmax0 = fmaxf(rmax0, __shfl_xor_sync(0xffffffffu, rmax0, off));
            rmax1 = fmaxf(rmax1, __shfl_xor_sync(0xffffffffu, rmax1, off));
        }
        float mn0 = fmaxf(mr0, rmax0), mn1 = fmaxf(mr1, rmax1);
        float corr0 = ex2(mr0 - mn0), corr1 = ex2(mr1 - mn1);
        mr0 = mn0; mr1 = mn1;

        float sum0 = 0.f, sum1 = 0.f;
#pragma unroll
        for (int j = 0; j < 8; j++) {
            s[j][0] = ex2(s[j][0] - mn0);
            s[j][1] = ex2(s[j][1] - mn0);
            s[j][2] = ex2(s[j][2] - mn1);
            s[j][3] = ex2(s[j][3] - mn1);
            sum0 += s[j][0] + s[j][1];
            sum1 += s[j][2] + s[j][3];
        }
#pragma unroll
        for (int off = 1; off <= 2; off <<= 1) {
            sum0 += __shfl_xor_sync(0xffffffffu, sum0, off);
            sum1 += __shfl_xor_sync(0xffffffffu, sum1, off);
        }
        lr0 = lr0 * corr0 + sum0;
        lr1 = lr1 * corr1 + sum1;
#pragma unroll
        for (int j = 0; j < 8; j++) {
            o[j][0] *= corr0; o[j][1] *= corr0;
            o[j][2] *= corr1; o[j][3] *= corr1;
        }

        // ---- pack P into PV A-fragments
        uint32_t pH[4][4];
#pragma unroll
        for (int kk = 0; kk < 4; kk++) {
            pH[kk][0] = pack_f16(s[2*kk][0],   s[2*kk][1]);
            pH[kk][1] = pack_f16(s[2*kk][2],   s[2*kk][3]);
            pH[kk][2] = pack_f16(s[2*kk+1][0], s[2*kk+1][1]);
            pH[kk][3] = pack_f16(s[2*kk+1][2], s[2*kk+1][3]);
        }

        // ---- O += P * V (ldmatrix.trans)
#pragma unroll
        for (int kk = 0; kk < 4; kk++) {
#pragma unroll
            for (int jp = 0; jp < 4; jp++) {
                uint32_t vF[4];
                uint32_t vd = VH + (kk*16 + (t & 7) + (((t >> 3) & 1) << 3)) * RB
                            + jp * 32 + ((t >> 4) << 4);
                ldsm4t(vF, vd);
                mma_f16(o[2*jp],   pH[kk], vF);
                mma_f16(o[2*jp+1], pH[kk], vF + 2);
            }
        }

        cur = (cur == 2) ? 0 : cur + 1;
        nxt = (nxt == 2) ? 0 : nxt + 1;
    }

    // ---- epilogue: ctx[b*S+s][h*64+e] as fp16 hi/lo
    const float inv0 = 1.0f / lr0, inv1 = 1.0f / lr1;
    const int srow = qb * 128 + w * 16 + (t >> 2);
    const int i2 = (t & 3) * 2;
#pragma unroll
    for (int nt = 0; nt < 8; nt++) {
        const int col = hcol + nt * 8 + i2;
        uint32_t hi, lo;
        size_t off0 = (rowbase + srow) * D_ + col;
        pack_hl_f16(o[nt][0] * inv0, o[nt][1] * inv0, hi, lo);
        *(uint32_t*)(g_cHi + off0) = hi;
        *(uint32_t*)(g_cLo + off0) = lo;
        size_t off1 = (rowbase + srow + 8) * D_ + col;
        pack_hl_f16(o[nt][2] * inv1, o[nt][3] * inv1, hi, lo);
        *(uint32_t*)(g_cHi + off1) = hi;
        *(uint32_t*)(g_cLo + off1) = lo;
    }
}

// ---------------------------------------------------------------------------
extern "C" void kernel_launch(void* const* d_in, const int* in_sizes, int n_in,
                              void* d_out, int out_size)
{
    const float* x  = (const float*)d_in[0];
    const float* Wq = (const float*)d_in[1];
    const float* bq = (const float*)d_in[2];
    const float* Wk = (const float*)d_in[3];
    const float* bk = (const float*)d_in[4];
    const float* Wv = (const float*)d_in[5];
    const float* bv = (const float*)d_in[6];
    const float* Wo = (const float*)d_in[7];
    const float* bo = (const float*)d_in[8];
    float* out = (float*)d_out;

    static bool attr_done = false;
    if (!attr_done) {
        cudaFuncSetAttribute(mma_gemm<0>, cudaFuncAttributeMaxDynamicSharedMemorySize, GEMM_SMEM);
        cudaFuncSetAttribute(mma_gemm<1>, cudaFuncAttributeMaxDynamicSharedMemorySize, GEMM_SMEM);
        cudaFuncSetAttribute(mma_attn,    cudaFuncAttributeMaxDynamicSharedMemorySize, ATTN_SMEM);
        attr_done = true;
    }

    // operand prep
    cvt_x_kernel<<<MTOT * D_ / 4 / 256, 256>>>(x);
    dim3 tT(32, 8);
    cvt_T3_kernel<<<dim3(D_/32, DH_/32, 3*H_), tT>>>(Wq, Wk, Wv);
    cvt_To_kernel<<<dim3(D_/32, D_/32),        tT>>>(Wo);

    // fused QKV projection: Q third 2-term, K/V thirds 1-term
    mma_gemm<0><<<dim3(NQKV/128, MTOT/128), 256, GEMM_SMEM>>>(bq, bk, bv, bo, out);

    // flash attention (all-fp16, 3-stage ring, 1 barrier/iter)
    mma_attn<<<dim3(S_/128, B_*H_), 256, ATTN_SMEM>>>();

    // output projection (2-term)
    mma_gemm<1><<<dim3(D_/128, MTOT/128), 256, GEMM_SMEM>>>(bq, bk, bv, bo, out);
}